// round 1
// baseline (speedup 1.0000x reference)
#include <cuda_runtime.h>
#include <math.h>

// Problem constants
#define BB   512
#define LL   71
#define DD   512
#define HH   8
#define DHH  64
#define SFIN 71
#define SFFF 128
#define MROWS (BB * LL)          // 36352 = 284 * 128 exactly

// Scratch (static device globals — no runtime allocation allowed)
__device__ float g_Q[BB * HH * LL * DHH];   // [b][h][l][dh], pre-scaled by 1/8
__device__ float g_K[BB * HH * LL * DHH];
__device__ float g_V[BB * HH * LL * DHH];
__device__ float g_attn[BB * LL * DD];      // [b][l][h*64+dh]

// ---------------------------------------------------------------------------
// Classic 128x128x8 SGEMM tile, 256 threads, 8x8 per-thread register block.
// M must be multiple of 128 (36352 = 284*128), N multiple of 128 (512), K=512.
// ---------------------------------------------------------------------------
__device__ __forceinline__ void sgemm_tile(const float* __restrict__ A,
                                           const float* __restrict__ W,
                                           float (&acc)[8][8])
{
    __shared__ __align__(16) float As[8][128];
    __shared__ __align__(16) float Bs[8][128];

    const int tid  = threadIdx.x;
    const int tRow = tid >> 4;        // 0..15
    const int tCol = tid & 15;        // 0..15
    const int mBase = blockIdx.y * 128;
    const int nBase = blockIdx.x * 128;

    const int aRow = tid >> 1;        // 0..127
    const int aCol = (tid & 1) << 2;  // 0 or 4
    const int bRow = tid >> 5;        // 0..7
    const int bCol = (tid & 31) << 2; // 0..124

    for (int k0 = 0; k0 < 512; k0 += 8) {
        float4 a4 = *(const float4*)(A + (size_t)(mBase + aRow) * 512 + k0 + aCol);
        As[aCol + 0][aRow] = a4.x;
        As[aCol + 1][aRow] = a4.y;
        As[aCol + 2][aRow] = a4.z;
        As[aCol + 3][aRow] = a4.w;
        *(float4*)&Bs[bRow][bCol] =
            *(const float4*)(W + (size_t)(k0 + bRow) * 512 + nBase + bCol);
        __syncthreads();

        #pragma unroll
        for (int k = 0; k < 8; k++) {
            float4 a0 = *(const float4*)&As[k][tRow * 8];
            float4 a1 = *(const float4*)&As[k][tRow * 8 + 4];
            float4 b0 = *(const float4*)&Bs[k][tCol * 8];
            float4 b1 = *(const float4*)&Bs[k][tCol * 8 + 4];
            float ra[8] = {a0.x, a0.y, a0.z, a0.w, a1.x, a1.y, a1.z, a1.w};
            float rb[8] = {b0.x, b0.y, b0.z, b0.w, b1.x, b1.y, b1.z, b1.w};
            #pragma unroll
            for (int i = 0; i < 8; i++)
                #pragma unroll
                for (int j = 0; j < 8; j++)
                    acc[i][j] = fmaf(ra[i], rb[j], acc[i][j]);
        }
        __syncthreads();
    }
}

// ---------------------------------------------------------------------------
// Kernel 1: fused QKV projections. grid = (4, 284, 3); z selects q/k/v.
// Epilogue scatters to [B,H,L,DH]; Q pre-scaled by 1/sqrt(64) = 0.125.
// ---------------------------------------------------------------------------
__global__ void __launch_bounds__(256) qkv_proj_kernel(
    const float* __restrict__ q_in, const float* __restrict__ k_in,
    const float* __restrict__ v_in,
    const float* __restrict__ Wq, const float* __restrict__ bq,
    const float* __restrict__ Wk, const float* __restrict__ bk,
    const float* __restrict__ Wv, const float* __restrict__ bv)
{
    const float *A, *W, *bias;
    float* out;
    float scale;
    if (blockIdx.z == 0)      { A = q_in; W = Wq; bias = bq; out = g_Q; scale = 0.125f; }
    else if (blockIdx.z == 1) { A = k_in; W = Wk; bias = bk; out = g_K; scale = 1.0f; }
    else                      { A = v_in; W = Wv; bias = bv; out = g_V; scale = 1.0f; }

    float acc[8][8];
    #pragma unroll
    for (int i = 0; i < 8; i++)
        #pragma unroll
        for (int j = 0; j < 8; j++) acc[i][j] = 0.f;

    sgemm_tile(A, W, acc);

    const int tid = threadIdx.x;
    const int tRow = tid >> 4, tCol = tid & 15;
    const int mBase = blockIdx.y * 128, nBase = blockIdx.x * 128;
    #pragma unroll
    for (int i = 0; i < 8; i++) {
        int m = mBase + tRow * 8 + i;
        int b = m / 71;
        int l = m - b * 71;
        #pragma unroll
        for (int j = 0; j < 8; j++) {
            int n  = nBase + tCol * 8 + j;
            int h  = n >> 6;
            int dh = n & 63;
            float v = (acc[i][j] + bias[n]) * scale;
            out[(((size_t)((b << 3) + h) * 71 + l) << 6) + dh] = v;
        }
    }
}

// ---------------------------------------------------------------------------
// Kernel 3: output projection -> d_out (row-major [B*L, D]).
// ---------------------------------------------------------------------------
__global__ void __launch_bounds__(256) out_proj_kernel(
    float* __restrict__ out, const float* __restrict__ Wo,
    const float* __restrict__ bo)
{
    float acc[8][8];
    #pragma unroll
    for (int i = 0; i < 8; i++)
        #pragma unroll
        for (int j = 0; j < 8; j++) acc[i][j] = 0.f;

    sgemm_tile(g_attn, Wo, acc);

    const int tid = threadIdx.x;
    const int tRow = tid >> 4, tCol = tid & 15;
    const int mBase = blockIdx.y * 128, nBase = blockIdx.x * 128;
    #pragma unroll
    for (int i = 0; i < 8; i++) {
        int m = mBase + tRow * 8 + i;
        #pragma unroll
        for (int j = 0; j < 8; j++) {
            int n = nBase + tCol * 8 + j;
            out[(size_t)m * 512 + n] = acc[i][j] + bo[n];
        }
    }
}

// ---------------------------------------------------------------------------
// Kernel 2: per-(b,h) attention with softmax-resnet.
// Block = one (b,h). 256 threads. Dynamic smem layout (floats):
//   sA  [0,      5120)  : Q^T [64][80] (zero-padded), later reused for V [71][64]
//   sKt [5120,  10240)  : K^T [64][80] (zero-padded)
//   sS  [10240, 16000)  : scores, stride 72, rows addressable to 79
//   sH  [16000, 26240)  : gelu hidden [80][128]
// ---------------------------------------------------------------------------
__global__ void __launch_bounds__(256) attn_kernel(
    const float* __restrict__ w1, const float* __restrict__ b1,
    const float* __restrict__ w2, const float* __restrict__ b2)
{
    extern __shared__ float sm[];
    float* sA  = sm;
    float* sKt = sm + 5120;
    float* sS  = sm + 10240;
    float* sH  = sm + 16000;

    const int tid = threadIdx.x;
    const int ty = tid >> 4, tx = tid & 15;
    const int bh = blockIdx.x;                 // b*8 + h
    const float* Q = g_Q + (size_t)bh * (71 * 64);
    const float* K = g_K + (size_t)bh * (71 * 64);
    const float* V = g_V + (size_t)bh * (71 * 64);

    // zero-pad Q^T / K^T regions (cols 71..79 must be 0)
    for (int i = tid; i < 5120; i += 256) { sA[i] = 0.f; sKt[i] = 0.f; }
    __syncthreads();
    for (int i = tid; i < 71 * 64; i += 256) {
        int l = i >> 6, dh = i & 63;
        sA[dh * 80 + l]  = Q[i];
        sKt[dh * 80 + l] = K[i];
    }
    __syncthreads();

    // ---- S = (Q/8) @ K^T : each thread a 5x5 tile of the padded 80x80 ----
    {
        const int r0 = ty * 5, c0 = tx * 5;
        float acc[5][5];
        #pragma unroll
        for (int i = 0; i < 5; i++)
            #pragma unroll
            for (int j = 0; j < 5; j++) acc[i][j] = 0.f;
        #pragma unroll 4
        for (int k = 0; k < 64; k++) {
            float ra[5], rb[5];
            #pragma unroll
            for (int i = 0; i < 5; i++) ra[i] = sA[k * 80 + r0 + i];
            #pragma unroll
            for (int j = 0; j < 5; j++) rb[j] = sKt[k * 80 + c0 + j];
            #pragma unroll
            for (int i = 0; i < 5; i++)
                #pragma unroll
                for (int j = 0; j < 5; j++)
                    acc[i][j] = fmaf(ra[i], rb[j], acc[i][j]);
        }
        #pragma unroll
        for (int i = 0; i < 5; i++) {
            int r = r0 + i;
            if (r < 71)
                #pragma unroll
                for (int j = 0; j < 5; j++) {
                    int c = c0 + j;
                    if (c < 71) sS[r * 72 + c] = acc[i][j];
                }
        }
    }
    __syncthreads();

    // V into sA (natural [l][dh] layout); no one reads sA until PV.
    for (int i = tid; i < 71 * 64; i += 256) sA[i] = V[i];

    // ---- H = gelu(S @ w1 + b1) : thread tile 5 rows x 8 cols ----
    {
        const int r0 = ty * 5, c0 = tx * 8;
        float acc[5][8];
        #pragma unroll
        for (int i = 0; i < 5; i++)
            #pragma unroll
            for (int j = 0; j < 8; j++) acc[i][j] = 0.f;
        for (int k = 0; k < 71; k++) {
            float sv[5];
            #pragma unroll
            for (int i = 0; i < 5; i++) sv[i] = sS[(r0 + i) * 72 + k];
            float4 w4a = __ldg((const float4*)(w1 + k * 128 + c0));
            float4 w4b = __ldg((const float4*)(w1 + k * 128 + c0 + 4));
            float wv[8] = {w4a.x, w4a.y, w4a.z, w4a.w, w4b.x, w4b.y, w4b.z, w4b.w};
            #pragma unroll
            for (int i = 0; i < 5; i++)
                #pragma unroll
                for (int j = 0; j < 8; j++)
                    acc[i][j] = fmaf(sv[i], wv[j], acc[i][j]);
        }
        float bv[8];
        #pragma unroll
        for (int j = 0; j < 8; j++) bv[j] = __ldg(b1 + c0 + j);
        #pragma unroll
        for (int i = 0; i < 5; i++)
            #pragma unroll
            for (int j = 0; j < 8; j++) {
                float x = acc[i][j] + bv[j];
                sH[(r0 + i) * 128 + c0 + j] =
                    0.5f * x * (1.f + erff(x * 0.70710678118654752f));
            }
    }
    __syncthreads();

    // ---- S += H @ w2 + b2 : thread tile 5x5 ----
    {
        const int r0 = ty * 5, c0 = tx * 5;
        float acc[5][5];
        #pragma unroll
        for (int i = 0; i < 5; i++)
            #pragma unroll
            for (int j = 0; j < 5; j++) acc[i][j] = 0.f;
        for (int f = 0; f < 128; f++) {
            float hv[5];
            #pragma unroll
            for (int i = 0; i < 5; i++) hv[i] = sH[(r0 + i) * 128 + f];
            float wv[5];
            #pragma unroll
            for (int j = 0; j < 5; j++) {
                int c = c0 + j;
                wv[j] = (c < 71) ? __ldg(w2 + f * 71 + c) : 0.f;
            }
            #pragma unroll
            for (int i = 0; i < 5; i++)
                #pragma unroll
                for (int j = 0; j < 5; j++)
                    acc[i][j] = fmaf(hv[i], wv[j], acc[i][j]);
        }
        #pragma unroll
        for (int i = 0; i < 5; i++) {
            int r = r0 + i;
            if (r < 71)
                #pragma unroll
                for (int j = 0; j < 5; j++) {
                    int c = c0 + j;
                    if (c < 71) sS[r * 72 + c] += acc[i][j] + __ldg(b2 + c);
                }
        }
    }
    __syncthreads();

    // ---- softmax over each row (71 elems), one warp per row ----
    {
        const int warp = tid >> 5, lane = tid & 31;
        for (int r = warp; r < 71; r += 8) {
            float* row = sS + r * 72;
            float m = -1e30f;
            for (int j = lane; j < 71; j += 32) m = fmaxf(m, row[j]);
            #pragma unroll
            for (int o = 16; o > 0; o >>= 1)
                m = fmaxf(m, __shfl_xor_sync(0xffffffffu, m, o));
            float s = 0.f;
            for (int j = lane; j < 71; j += 32) {
                float e = __expf(row[j] - m);
                row[j] = e;
                s += e;
            }
            #pragma unroll
            for (int o = 16; o > 0; o >>= 1)
                s += __shfl_xor_sync(0xffffffffu, s, o);
            float inv = 1.f / s;
            for (int j = lane; j < 71; j += 32) row[j] *= inv;
        }
    }
    __syncthreads();

    // ---- attn = P @ V : thread tile 5 rows x 4 cols ----
    {
        const int r0 = ty * 5, c0 = tx * 4;
        float acc[5][4];
        #pragma unroll
        for (int i = 0; i < 5; i++)
            #pragma unroll
            for (int j = 0; j < 4; j++) acc[i][j] = 0.f;
        for (int k = 0; k < 71; k++) {
            float pv[5];
            #pragma unroll
            for (int i = 0; i < 5; i++) pv[i] = sS[(r0 + i) * 72 + k];
            float vv[4];
            #pragma unroll
            for (int j = 0; j < 4; j++) vv[j] = sA[k * 64 + c0 + j];
            #pragma unroll
            for (int i = 0; i < 5; i++)
                #pragma unroll
                for (int j = 0; j < 4; j++)
                    acc[i][j] = fmaf(pv[i], vv[j], acc[i][j]);
        }
        const int b = bh >> 3, h = bh & 7;
        #pragma unroll
        for (int i = 0; i < 5; i++) {
            int r = r0 + i;
            if (r < 71) {
                float* o = g_attn + ((size_t)(b * 71 + r)) * 512 + h * 64 + c0;
                #pragma unroll
                for (int j = 0; j < 4; j++) o[j] = acc[i][j];
            }
        }
    }
}

// ---------------------------------------------------------------------------
extern "C" void kernel_launch(void* const* d_in, const int* in_sizes, int n_in,
                              void* d_out, int out_size)
{
    const float* query = (const float*)d_in[0];
    const float* key   = (const float*)d_in[1];
    const float* value = (const float*)d_in[2];
    const float* Wq = (const float*)d_in[3];
    const float* bq = (const float*)d_in[4];
    const float* Wk = (const float*)d_in[5];
    const float* bk = (const float*)d_in[6];
    const float* Wv = (const float*)d_in[7];
    const float* bv = (const float*)d_in[8];
    const float* Wo = (const float*)d_in[9];
    const float* bo = (const float*)d_in[10];
    const float* sf_w1 = (const float*)d_in[11];
    const float* sf_b1 = (const float*)d_in[12];
    const float* sf_w2 = (const float*)d_in[13];
    const float* sf_b2 = (const float*)d_in[14];
    float* out = (float*)d_out;

    // 1) QKV projections
    dim3 g1(4, 284, 3);
    qkv_proj_kernel<<<g1, 256>>>(query, key, value, Wq, bq, Wk, bk, Wv, bv);

    // 2) attention core (102.5 KB dynamic smem -> 2 CTAs/SM)
    const int smem_bytes = 26240 * sizeof(float);
    cudaFuncSetAttribute(attn_kernel, cudaFuncAttributeMaxDynamicSharedMemorySize,
                         smem_bytes);
    attn_kernel<<<BB * HH, 256, smem_bytes>>>(sf_w1, sf_b1, sf_w2, sf_b2);

    // 3) output projection
    dim3 g3(4, 284);
    out_proj_kernel<<<g3, 256>>>(out, Wo, bo);
}

// round 2
// speedup vs baseline: 1.9993x; 1.9993x over previous
#include <cuda_runtime.h>
#include <math.h>

// Problem constants
#define BB   512
#define LL   71
#define DD   512
#define HH   8
#define DHH  64
#define MROWS (BB * LL)          // 36352 = 284*128 = 1136*32

// ---------------------------------------------------------------------------
// Scratch (static device globals — no runtime allocation allowed)
// ---------------------------------------------------------------------------
__device__ float g_Tq[DD * MROWS];        // transposed tf32 activations [512][M]
__device__ float g_Tk[DD * MROWS];
__device__ float g_Tv[DD * MROWS];
__device__ float g_Q[BB * HH * LL * DHH]; // [b][h][l][dh], Q pre-scaled by 1/8
__device__ float g_K[BB * HH * LL * DHH];
__device__ float g_V[BB * HH * LL * DHH];
__device__ float g_attn[MROWS * DD];      // [b*l][h*64+dh] row-major
__device__ float g_attnT[DD * MROWS];     // transposed tf32 [512][M]

__device__ __forceinline__ float to_tf32(float x) {
    float y;
    asm("cvt.rna.tf32.f32 %0, %1;" : "=f"(y) : "f"(x));
    return y;
}

// ---------------------------------------------------------------------------
// Transpose + tf32 convert: in [M][512] fp32 -> out [512][M] tf32-in-fp32.
// grid (M/32, 512/32, nz); 256 threads (32x8).
// ---------------------------------------------------------------------------
__global__ void __launch_bounds__(256) transpose_cvt_kernel(
    const float* __restrict__ in0, const float* __restrict__ in1,
    const float* __restrict__ in2,
    float* __restrict__ out0, float* __restrict__ out1, float* __restrict__ out2)
{
    __shared__ float sm[32][33];
    const float* in = (blockIdx.z == 0) ? in0 : (blockIdx.z == 1 ? in1 : in2);
    float* out      = (blockIdx.z == 0) ? out0 : (blockIdx.z == 1 ? out1 : out2);
    const int m0 = blockIdx.x * 32, k0 = blockIdx.y * 32;
    const int tx = threadIdx.x & 31, ty = threadIdx.x >> 5;
    #pragma unroll
    for (int j = 0; j < 4; j++)
        sm[ty + 8 * j][tx] = in[(size_t)(m0 + ty + 8 * j) * 512 + k0 + tx];
    __syncthreads();
    #pragma unroll
    for (int j = 0; j < 4; j++)
        out[(size_t)(k0 + ty + 8 * j) * MROWS + m0 + tx] = to_tf32(sm[tx][ty + 8 * j]);
}

// ---------------------------------------------------------------------------
// tf32 mma.sync GEMM core: CTA 128x128, K=512, KC=32, double-buffered smem.
// 8 warps as 2(M)x4(N); warp tile 64x32; m16n8k8 tiles 4x4 per warp.
// AT is k-major [512][MROWS], already tf32. W is [512][512] fp32 (cvt on STS).
// Result in c[im][in][4] per thread.
// ---------------------------------------------------------------------------
__device__ __forceinline__ void gemm_tf32_ctile(
    const float* __restrict__ AT, const float* __restrict__ W,
    float (&c)[4][4][4])
{
    extern __shared__ float sm[];
    float* As = sm;            // [2][32][136]
    float* Bs = sm + 8704;     // [2][32][136]

    const int tid  = threadIdx.x;
    const int lane = tid & 31;
    const int warp = tid >> 5;
    const int mBase = blockIdx.y * 128;
    const int nBase = blockIdx.x * 128;

    #pragma unroll
    for (int im = 0; im < 4; im++)
        #pragma unroll
        for (int in = 0; in < 4; in++)
            #pragma unroll
            for (int q = 0; q < 4; q++) c[im][in][q] = 0.f;

    auto ldgA = [&](int kt, float4 (&ra)[4]) {
        #pragma unroll
        for (int it = 0; it < 4; it++) {
            int idx = it * 256 + tid;
            int k = idx >> 5, m4 = (idx & 31) << 2;
            ra[it] = *(const float4*)(AT + (size_t)(kt * 32 + k) * MROWS + mBase + m4);
        }
    };
    auto ldgB = [&](int kt, float4 (&rb)[4]) {
        #pragma unroll
        for (int it = 0; it < 4; it++) {
            int idx = it * 256 + tid;
            int k = idx >> 5, n4 = (idx & 31) << 2;
            rb[it] = *(const float4*)(W + (size_t)(kt * 32 + k) * 512 + nBase + n4);
        }
    };
    auto stsA = [&](int buf, float4 (&ra)[4]) {
        #pragma unroll
        for (int it = 0; it < 4; it++) {
            int idx = it * 256 + tid;
            int k = idx >> 5, m4 = (idx & 31) << 2;
            *(float4*)&As[buf * 4352 + k * 136 + m4] = ra[it];
        }
    };
    auto stsB = [&](int buf, float4 (&rb)[4]) {
        #pragma unroll
        for (int it = 0; it < 4; it++) {
            int idx = it * 256 + tid;
            int k = idx >> 5, n4 = (idx & 31) << 2;
            float4 v = rb[it];
            v.x = to_tf32(v.x); v.y = to_tf32(v.y);
            v.z = to_tf32(v.z); v.w = to_tf32(v.w);
            *(float4*)&Bs[buf * 4352 + k * 136 + n4] = v;
        }
    };
    auto compute = [&](int buf) {
        const float* Asb = As + buf * 4352;
        const float* Bsb = Bs + buf * 4352;
        const int r0 = (warp & 1) * 64 + (lane >> 2);
        const int n0 = (warp >> 1) * 32 + (lane >> 2);
        #pragma unroll
        for (int s = 0; s < 4; s++) {
            const int kk = s * 8 + (lane & 3);
            unsigned a[4][4], b[4][2];
            #pragma unroll
            for (int im = 0; im < 4; im++) {
                a[im][0] = __float_as_uint(Asb[kk * 136 + r0 + im * 16]);
                a[im][1] = __float_as_uint(Asb[kk * 136 + r0 + im * 16 + 8]);
                a[im][2] = __float_as_uint(Asb[(kk + 4) * 136 + r0 + im * 16]);
                a[im][3] = __float_as_uint(Asb[(kk + 4) * 136 + r0 + im * 16 + 8]);
            }
            #pragma unroll
            for (int in = 0; in < 4; in++) {
                b[in][0] = __float_as_uint(Bsb[kk * 136 + n0 + in * 8]);
                b[in][1] = __float_as_uint(Bsb[(kk + 4) * 136 + n0 + in * 8]);
            }
            #pragma unroll
            for (int im = 0; im < 4; im++)
                #pragma unroll
                for (int in = 0; in < 4; in++)
                    asm volatile(
                        "mma.sync.aligned.m16n8k8.row.col.f32.tf32.tf32.f32 "
                        "{%0,%1,%2,%3}, {%4,%5,%6,%7}, {%8,%9}, {%0,%1,%2,%3};"
                        : "+f"(c[im][in][0]), "+f"(c[im][in][1]),
                          "+f"(c[im][in][2]), "+f"(c[im][in][3])
                        : "r"(a[im][0]), "r"(a[im][1]), "r"(a[im][2]), "r"(a[im][3]),
                          "r"(b[in][0]), "r"(b[in][1]));
        }
    };

    float4 ra[4], rb[4];
    ldgA(0, ra); ldgB(0, rb);
    stsA(0, ra); stsB(0, rb);
    __syncthreads();
    #pragma unroll 1
    for (int kt = 0; kt < 16; kt++) {
        const int cur = kt & 1;
        if (kt < 15) { ldgA(kt + 1, ra); ldgB(kt + 1, rb); }
        compute(cur);
        if (kt < 15) { stsA(cur ^ 1, ra); stsB(cur ^ 1, rb); }
        __syncthreads();
    }
}

// ---------------------------------------------------------------------------
// QKV projection: grid (4, 284, 3). Scatter epilogue to [B,H,L,DH].
// ---------------------------------------------------------------------------
__global__ void __launch_bounds__(256) qkv_gemm_kernel(
    const float* __restrict__ Wq, const float* __restrict__ bq,
    const float* __restrict__ Wk, const float* __restrict__ bk,
    const float* __restrict__ Wv, const float* __restrict__ bv)
{
    const float* AT; const float* W; const float* bias; float* out; float scale;
    if (blockIdx.z == 0)      { AT = g_Tq; W = Wq; bias = bq; out = g_Q; scale = 0.125f; }
    else if (blockIdx.z == 1) { AT = g_Tk; W = Wk; bias = bk; out = g_K; scale = 1.0f; }
    else                      { AT = g_Tv; W = Wv; bias = bv; out = g_V; scale = 1.0f; }

    float c[4][4][4];
    gemm_tf32_ctile(AT, W, c);

    const int lane = threadIdx.x & 31, warp = threadIdx.x >> 5;
    const int mBase = blockIdx.y * 128, nBase = blockIdx.x * 128;

    float bv2[4][2];
    #pragma unroll
    for (int in = 0; in < 4; in++) {
        int cg = nBase + (warp >> 1) * 32 + in * 8 + 2 * (lane & 3);
        bv2[in][0] = bias[cg]; bv2[in][1] = bias[cg + 1];
    }
    #pragma unroll
    for (int im = 0; im < 4; im++) {
        int rg0 = mBase + (warp & 1) * 64 + im * 16 + (lane >> 2);
        int rg1 = rg0 + 8;
        int b0 = rg0 / 71, l0 = rg0 - b0 * 71;
        int b1 = rg1 / 71, l1 = rg1 - b1 * 71;
        #pragma unroll
        for (int in = 0; in < 4; in++) {
            int cg = nBase + (warp >> 1) * 32 + in * 8 + 2 * (lane & 3);
            int h = cg >> 6, dh = cg & 63;
            float2 v0 = make_float2((c[im][in][0] + bv2[in][0]) * scale,
                                    (c[im][in][1] + bv2[in][1]) * scale);
            float2 v1 = make_float2((c[im][in][2] + bv2[in][0]) * scale,
                                    (c[im][in][3] + bv2[in][1]) * scale);
            *(float2*)&out[(((size_t)(b0 * 8 + h) * 71 + l0) << 6) + dh] = v0;
            *(float2*)&out[(((size_t)(b1 * 8 + h) * 71 + l1) << 6) + dh] = v1;
        }
    }
}

// ---------------------------------------------------------------------------
// Output projection: grid (4, 284). Plain row-major epilogue to d_out.
// ---------------------------------------------------------------------------
__global__ void __launch_bounds__(256) out_gemm_kernel(
    float* __restrict__ out, const float* __restrict__ Wo,
    const float* __restrict__ bo)
{
    float c[4][4][4];
    gemm_tf32_ctile(g_attnT, Wo, c);

    const int lane = threadIdx.x & 31, warp = threadIdx.x >> 5;
    const int mBase = blockIdx.y * 128, nBase = blockIdx.x * 128;

    float bv2[4][2];
    #pragma unroll
    for (int in = 0; in < 4; in++) {
        int cg = nBase + (warp >> 1) * 32 + in * 8 + 2 * (lane & 3);
        bv2[in][0] = bo[cg]; bv2[in][1] = bo[cg + 1];
    }
    #pragma unroll
    for (int im = 0; im < 4; im++) {
        int rg0 = mBase + (warp & 1) * 64 + im * 16 + (lane >> 2);
        int rg1 = rg0 + 8;
        #pragma unroll
        for (int in = 0; in < 4; in++) {
            int cg = nBase + (warp >> 1) * 32 + in * 8 + 2 * (lane & 3);
            float2 v0 = make_float2(c[im][in][0] + bv2[in][0], c[im][in][1] + bv2[in][1]);
            float2 v1 = make_float2(c[im][in][2] + bv2[in][0], c[im][in][3] + bv2[in][1]);
            *(float2*)&out[(size_t)rg0 * 512 + cg] = v0;
            *(float2*)&out[(size_t)rg1 * 512 + cg] = v1;
        }
    }
}

// ---------------------------------------------------------------------------
// Attention core (unchanged from R1): per-(b,h) block, fp32, 256 threads.
// smem: sA [0,5120) Q^T [64][80] then V; sKt [5120,10240); sS [10240,16000)
// stride 72; sH [16000,26240) [80][128].
// ---------------------------------------------------------------------------
__global__ void __launch_bounds__(256) attn_kernel(
    const float* __restrict__ w1, const float* __restrict__ b1,
    const float* __restrict__ w2, const float* __restrict__ b2)
{
    extern __shared__ float smf[];
    float* sA  = smf;
    float* sKt = smf + 5120;
    float* sS  = smf + 10240;
    float* sH  = smf + 16000;

    const int tid = threadIdx.x;
    const int ty = tid >> 4, tx = tid & 15;
    const int bh = blockIdx.x;
    const float* Q = g_Q + (size_t)bh * (71 * 64);
    const float* K = g_K + (size_t)bh * (71 * 64);
    const float* V = g_V + (size_t)bh * (71 * 64);

    for (int i = tid; i < 5120; i += 256) { sA[i] = 0.f; sKt[i] = 0.f; }
    __syncthreads();
    for (int i = tid; i < 71 * 64; i += 256) {
        int l = i >> 6, dh = i & 63;
        sA[dh * 80 + l]  = Q[i];
        sKt[dh * 80 + l] = K[i];
    }
    __syncthreads();

    // S = (Q/8) @ K^T
    {
        const int r0 = ty * 5, c0 = tx * 5;
        float acc[5][5];
        #pragma unroll
        for (int i = 0; i < 5; i++)
            #pragma unroll
            for (int j = 0; j < 5; j++) acc[i][j] = 0.f;
        #pragma unroll 4
        for (int k = 0; k < 64; k++) {
            float rA[5], rB[5];
            #pragma unroll
            for (int i = 0; i < 5; i++) rA[i] = sA[k * 80 + r0 + i];
            #pragma unroll
            for (int j = 0; j < 5; j++) rB[j] = sKt[k * 80 + c0 + j];
            #pragma unroll
            for (int i = 0; i < 5; i++)
                #pragma unroll
                for (int j = 0; j < 5; j++)
                    acc[i][j] = fmaf(rA[i], rB[j], acc[i][j]);
        }
        #pragma unroll
        for (int i = 0; i < 5; i++) {
            int r = r0 + i;
            if (r < 71)
                #pragma unroll
                for (int j = 0; j < 5; j++) {
                    int cc = c0 + j;
                    if (cc < 71) sS[r * 72 + cc] = acc[i][j];
                }
        }
    }
    __syncthreads();

    for (int i = tid; i < 71 * 64; i += 256) sA[i] = V[i];

    // H = gelu(S @ w1 + b1)
    {
        const int r0 = ty * 5, c0 = tx * 8;
        float acc[5][8];
        #pragma unroll
        for (int i = 0; i < 5; i++)
            #pragma unroll
            for (int j = 0; j < 8; j++) acc[i][j] = 0.f;
        for (int k = 0; k < 71; k++) {
            float sv[5];
            #pragma unroll
            for (int i = 0; i < 5; i++) sv[i] = sS[(r0 + i) * 72 + k];
            float4 w4a = __ldg((const float4*)(w1 + k * 128 + c0));
            float4 w4b = __ldg((const float4*)(w1 + k * 128 + c0 + 4));
            float wv[8] = {w4a.x, w4a.y, w4a.z, w4a.w, w4b.x, w4b.y, w4b.z, w4b.w};
            #pragma unroll
            for (int i = 0; i < 5; i++)
                #pragma unroll
                for (int j = 0; j < 8; j++)
                    acc[i][j] = fmaf(sv[i], wv[j], acc[i][j]);
        }
        float bvv[8];
        #pragma unroll
        for (int j = 0; j < 8; j++) bvv[j] = __ldg(b1 + c0 + j);
        #pragma unroll
        for (int i = 0; i < 5; i++)
            #pragma unroll
            for (int j = 0; j < 8; j++) {
                float x = acc[i][j] + bvv[j];
                sH[(r0 + i) * 128 + c0 + j] =
                    0.5f * x * (1.f + erff(x * 0.70710678118654752f));
            }
    }
    __syncthreads();

    // S += H @ w2 + b2
    {
        const int r0 = ty * 5, c0 = tx * 5;
        float acc[5][5];
        #pragma unroll
        for (int i = 0; i < 5; i++)
            #pragma unroll
            for (int j = 0; j < 5; j++) acc[i][j] = 0.f;
        for (int f = 0; f < 128; f++) {
            float hv[5];
            #pragma unroll
            for (int i = 0; i < 5; i++) hv[i] = sH[(r0 + i) * 128 + f];
            float wv[5];
            #pragma unroll
            for (int j = 0; j < 5; j++) {
                int cc = c0 + j;
                wv[j] = (cc < 71) ? __ldg(w2 + f * 71 + cc) : 0.f;
            }
            #pragma unroll
            for (int i = 0; i < 5; i++)
                #pragma unroll
                for (int j = 0; j < 5; j++)
                    acc[i][j] = fmaf(hv[i], wv[j], acc[i][j]);
        }
        #pragma unroll
        for (int i = 0; i < 5; i++) {
            int r = r0 + i;
            if (r < 71)
                #pragma unroll
                for (int j = 0; j < 5; j++) {
                    int cc = c0 + j;
                    if (cc < 71) sS[r * 72 + cc] += acc[i][j] + __ldg(b2 + cc);
                }
        }
    }
    __syncthreads();

    // softmax per row
    {
        const int warp = tid >> 5, lanei = tid & 31;
        for (int r = warp; r < 71; r += 8) {
            float* row = sS + r * 72;
            float m = -1e30f;
            for (int j = lanei; j < 71; j += 32) m = fmaxf(m, row[j]);
            #pragma unroll
            for (int o = 16; o > 0; o >>= 1)
                m = fmaxf(m, __shfl_xor_sync(0xffffffffu, m, o));
            float s = 0.f;
            for (int j = lanei; j < 71; j += 32) {
                float e = __expf(row[j] - m);
                row[j] = e;
                s += e;
            }
            #pragma unroll
            for (int o = 16; o > 0; o >>= 1)
                s += __shfl_xor_sync(0xffffffffu, s, o);
            float inv = 1.f / s;
            for (int j = lanei; j < 71; j += 32) row[j] *= inv;
        }
    }
    __syncthreads();

    // attn = P @ V -> g_attn row-major
    {
        const int r0 = ty * 5, c0 = tx * 4;
        float acc[5][4];
        #pragma unroll
        for (int i = 0; i < 5; i++)
            #pragma unroll
            for (int j = 0; j < 4; j++) acc[i][j] = 0.f;
        for (int k = 0; k < 71; k++) {
            float pv[5];
            #pragma unroll
            for (int i = 0; i < 5; i++) pv[i] = sS[(r0 + i) * 72 + k];
            float vv[4];
            #pragma unroll
            for (int j = 0; j < 4; j++) vv[j] = sA[k * 64 + c0 + j];
            #pragma unroll
            for (int i = 0; i < 5; i++)
                #pragma unroll
                for (int j = 0; j < 4; j++)
                    acc[i][j] = fmaf(pv[i], vv[j], acc[i][j]);
        }
        const int b = bh >> 3, h = bh & 7;
        #pragma unroll
        for (int i = 0; i < 5; i++) {
            int r = r0 + i;
            if (r < 71) {
                float* o = g_attn + ((size_t)(b * 71 + r)) * 512 + h * 64 + c0;
                #pragma unroll
                for (int j = 0; j < 4; j++) o[j] = acc[i][j];
            }
        }
    }
}

// ---------------------------------------------------------------------------
extern "C" void kernel_launch(void* const* d_in, const int* in_sizes, int n_in,
                              void* d_out, int out_size)
{
    const float* query = (const float*)d_in[0];
    const float* key   = (const float*)d_in[1];
    const float* value = (const float*)d_in[2];
    const float* Wq = (const float*)d_in[3];
    const float* bq = (const float*)d_in[4];
    const float* Wk = (const float*)d_in[5];
    const float* bk = (const float*)d_in[6];
    const float* Wv = (const float*)d_in[7];
    const float* bv = (const float*)d_in[8];
    const float* Wo = (const float*)d_in[9];
    const float* bo = (const float*)d_in[10];
    const float* sf_w1 = (const float*)d_in[11];
    const float* sf_b1 = (const float*)d_in[12];
    const float* sf_w2 = (const float*)d_in[13];
    const float* sf_b2 = (const float*)d_in[14];
    float* out = (float*)d_out;

    float *dTq, *dTk, *dTv, *dAttn, *dAttnT;
    cudaGetSymbolAddress((void**)&dTq, g_Tq);
    cudaGetSymbolAddress((void**)&dTk, g_Tk);
    cudaGetSymbolAddress((void**)&dTv, g_Tv);
    cudaGetSymbolAddress((void**)&dAttn, g_attn);
    cudaGetSymbolAddress((void**)&dAttnT, g_attnT);

    const int gemm_smem = 17408 * sizeof(float);   // 69632 B
    cudaFuncSetAttribute(qkv_gemm_kernel, cudaFuncAttributeMaxDynamicSharedMemorySize, gemm_smem);
    cudaFuncSetAttribute(out_gemm_kernel, cudaFuncAttributeMaxDynamicSharedMemorySize, gemm_smem);
    const int attn_smem = 26240 * sizeof(float);   // 104960 B
    cudaFuncSetAttribute(attn_kernel, cudaFuncAttributeMaxDynamicSharedMemorySize, attn_smem);

    // 1) transpose+cvt activations
    dim3 gt(MROWS / 32, 16, 3);
    transpose_cvt_kernel<<<gt, 256>>>(query, key, value, dTq, dTk, dTv);

    // 2) QKV projections (tf32 tensor cores)
    dim3 g1(4, 284, 3);
    qkv_gemm_kernel<<<g1, 256, gemm_smem>>>(Wq, bq, Wk, bk, Wv, bv);

    // 3) attention core
    attn_kernel<<<BB * HH, 256, attn_smem>>>(sf_w1, sf_b1, sf_w2, sf_b2);

    // 4) transpose+cvt attention output
    dim3 gt2(MROWS / 32, 16, 1);
    transpose_cvt_kernel<<<gt2, 256>>>(dAttn, dAttn, dAttn, dAttnT, dAttnT, dAttnT);

    // 5) output projection
    dim3 g3(4, 284);
    out_gemm_kernel<<<g3, 256, gemm_smem>>>(out, Wo, bo);
}

// round 3
// speedup vs baseline: 2.6733x; 1.3371x over previous
#include <cuda_runtime.h>
#include <math.h>

// Problem constants
#define BB   512
#define LL   71
#define DD   512
#define HH   8
#define DHH  64
#define MROWS (BB * LL)          // 36352
#define NHEADS (BB * HH)         // 4096
#define HEAD_ELEMS (LL * DHH)    // 4544

// ---------------------------------------------------------------------------
// Scratch (static device globals)
// ---------------------------------------------------------------------------
__device__ float g_Tq[DD * MROWS];        // transposed tf32 activations [512][M]
__device__ float g_Tk[DD * MROWS];
__device__ float g_Tv[DD * MROWS];
__device__ float g_Qt[NHEADS * HEAD_ELEMS]; // [bh][dh][l], Q pre-scaled by 1/8
__device__ float g_Kt[NHEADS * HEAD_ELEMS]; // [bh][dh][l]
__device__ float g_V [NHEADS * HEAD_ELEMS]; // [bh][l][dh]
__device__ float g_attnT[DD * MROWS];       // [d][m] tf32 (k-major for out proj)

__device__ __forceinline__ float to_tf32(float x) {
    float y;
    asm("cvt.rna.tf32.f32 %0, %1;" : "=f"(y) : "f"(x));
    return y;
}

__device__ __forceinline__ void mma_tf32(float* c, const unsigned* a, const unsigned* b) {
    asm volatile(
        "mma.sync.aligned.m16n8k8.row.col.f32.tf32.tf32.f32 "
        "{%0,%1,%2,%3}, {%4,%5,%6,%7}, {%8,%9}, {%0,%1,%2,%3};"
        : "+f"(c[0]), "+f"(c[1]), "+f"(c[2]), "+f"(c[3])
        : "r"(a[0]), "r"(a[1]), "r"(a[2]), "r"(a[3]), "r"(b[0]), "r"(b[1]));
}

// A fragment: A[m][k] stored k-major base[k*stride + m]
#define LDA(frag, base, stride, mt, kk) { \
    const float* p_ = (base) + (kk) * (stride) + (mt) * 16 + (lane >> 2); \
    frag[0] = __float_as_uint(p_[0]); \
    frag[1] = __float_as_uint(p_[8]); \
    frag[2] = __float_as_uint(p_[(stride) * 4]); \
    frag[3] = __float_as_uint(p_[(stride) * 4 + 8]); }

// B fragment: B[k][n] k-major base[k*stride + n]
#define LDB(frag, base, stride, nt, kk) { \
    const float* p_ = (base) + (kk) * (stride) + (nt) * 8 + (lane >> 2); \
    frag[0] = __float_as_uint(p_[0]); \
    frag[1] = __float_as_uint(p_[(stride) * 4]); }

// ---------------------------------------------------------------------------
// Transpose + tf32 convert: in [M][512] fp32 -> out [512][M] tf32.
// ---------------------------------------------------------------------------
__global__ void __launch_bounds__(256) transpose_cvt_kernel(
    const float* __restrict__ in0, const float* __restrict__ in1,
    const float* __restrict__ in2,
    float* __restrict__ out0, float* __restrict__ out1, float* __restrict__ out2)
{
    __shared__ float sm[32][33];
    const float* in = (blockIdx.z == 0) ? in0 : (blockIdx.z == 1 ? in1 : in2);
    float* out      = (blockIdx.z == 0) ? out0 : (blockIdx.z == 1 ? out1 : out2);
    const int m0 = blockIdx.x * 32, k0 = blockIdx.y * 32;
    const int tx = threadIdx.x & 31, ty = threadIdx.x >> 5;
    #pragma unroll
    for (int j = 0; j < 4; j++)
        sm[ty + 8 * j][tx] = in[(size_t)(m0 + ty + 8 * j) * 512 + k0 + tx];
    __syncthreads();
    #pragma unroll
    for (int j = 0; j < 4; j++)
        out[(size_t)(k0 + ty + 8 * j) * MROWS + m0 + tx] = to_tf32(sm[tx][ty + 8 * j]);
}

// ---------------------------------------------------------------------------
// tf32 GEMM core: CTA 128x128, K=512, KC=32, double-buffered smem.
// ---------------------------------------------------------------------------
__device__ __forceinline__ void gemm_tf32_ctile(
    const float* __restrict__ AT, const float* __restrict__ W,
    float (&c)[4][4][4])
{
    extern __shared__ float sm[];
    float* As = sm;            // [2][32][136]
    float* Bs = sm + 8704;

    const int tid  = threadIdx.x;
    const int lane = tid & 31;
    const int warp = tid >> 5;
    const int mBase = blockIdx.y * 128;
    const int nBase = blockIdx.x * 128;

    #pragma unroll
    for (int im = 0; im < 4; im++)
        #pragma unroll
        for (int in = 0; in < 4; in++)
            #pragma unroll
            for (int q = 0; q < 4; q++) c[im][in][q] = 0.f;

    auto ldgA = [&](int kt, float4 (&ra)[4]) {
        #pragma unroll
        for (int it = 0; it < 4; it++) {
            int idx = it * 256 + tid;
            int k = idx >> 5, m4 = (idx & 31) << 2;
            ra[it] = *(const float4*)(AT + (size_t)(kt * 32 + k) * MROWS + mBase + m4);
        }
    };
    auto ldgB = [&](int kt, float4 (&rb)[4]) {
        #pragma unroll
        for (int it = 0; it < 4; it++) {
            int idx = it * 256 + tid;
            int k = idx >> 5, n4 = (idx & 31) << 2;
            rb[it] = *(const float4*)(W + (size_t)(kt * 32 + k) * 512 + nBase + n4);
        }
    };
    auto stsA = [&](int buf, float4 (&ra)[4]) {
        #pragma unroll
        for (int it = 0; it < 4; it++) {
            int idx = it * 256 + tid;
            int k = idx >> 5, m4 = (idx & 31) << 2;
            *(float4*)&As[buf * 4352 + k * 136 + m4] = ra[it];
        }
    };
    auto stsB = [&](int buf, float4 (&rb)[4]) {
        #pragma unroll
        for (int it = 0; it < 4; it++) {
            int idx = it * 256 + tid;
            int k = idx >> 5, n4 = (idx & 31) << 2;
            float4 v = rb[it];
            v.x = to_tf32(v.x); v.y = to_tf32(v.y);
            v.z = to_tf32(v.z); v.w = to_tf32(v.w);
            *(float4*)&Bs[buf * 4352 + k * 136 + n4] = v;
        }
    };
    auto compute = [&](int buf) {
        const float* Asb = As + buf * 4352;
        const float* Bsb = Bs + buf * 4352;
        const int r0 = (warp & 1) * 64 + (lane >> 2);
        const int n0 = (warp >> 1) * 32 + (lane >> 2);
        #pragma unroll
        for (int s = 0; s < 4; s++) {
            const int kk = s * 8 + (lane & 3);
            unsigned a[4][4], b[4][2];
            #pragma unroll
            for (int im = 0; im < 4; im++) {
                a[im][0] = __float_as_uint(Asb[kk * 136 + r0 + im * 16]);
                a[im][1] = __float_as_uint(Asb[kk * 136 + r0 + im * 16 + 8]);
                a[im][2] = __float_as_uint(Asb[(kk + 4) * 136 + r0 + im * 16]);
                a[im][3] = __float_as_uint(Asb[(kk + 4) * 136 + r0 + im * 16 + 8]);
            }
            #pragma unroll
            for (int in = 0; in < 4; in++) {
                b[in][0] = __float_as_uint(Bsb[kk * 136 + n0 + in * 8]);
                b[in][1] = __float_as_uint(Bsb[(kk + 4) * 136 + n0 + in * 8]);
            }
            #pragma unroll
            for (int im = 0; im < 4; im++)
                #pragma unroll
                for (int in = 0; in < 4; in++)
                    mma_tf32(c[im][in], a[im], b[in]);
        }
    };

    float4 ra[4], rb[4];
    ldgA(0, ra); ldgB(0, rb);
    stsA(0, ra); stsB(0, rb);
    __syncthreads();
    #pragma unroll 1
    for (int kt = 0; kt < 16; kt++) {
        const int cur = kt & 1;
        if (kt < 15) { ldgA(kt + 1, ra); ldgB(kt + 1, rb); }
        compute(cur);
        if (kt < 15) { stsA(cur ^ 1, ra); stsB(cur ^ 1, rb); }
        __syncthreads();
    }
}

// ---------------------------------------------------------------------------
// QKV projection: grid (4, 284, 3). Q/K scatter transposed [bh][dh][l];
// V in [bh][l][dh].
// ---------------------------------------------------------------------------
__global__ void __launch_bounds__(256) qkv_gemm_kernel(
    const float* __restrict__ Wq, const float* __restrict__ bq,
    const float* __restrict__ Wk, const float* __restrict__ bk,
    const float* __restrict__ Wv, const float* __restrict__ bv)
{
    const float* AT; const float* W; const float* bias; float* out; float scale;
    if (blockIdx.z == 0)      { AT = g_Tq; W = Wq; bias = bq; out = g_Qt; scale = 0.125f; }
    else if (blockIdx.z == 1) { AT = g_Tk; W = Wk; bias = bk; out = g_Kt; scale = 1.0f; }
    else                      { AT = g_Tv; W = Wv; bias = bv; out = g_V;  scale = 1.0f; }

    float c[4][4][4];
    gemm_tf32_ctile(AT, W, c);

    const int lane = threadIdx.x & 31, warp = threadIdx.x >> 5;
    const int mBase = blockIdx.y * 128, nBase = blockIdx.x * 128;

    float bv2[4][2];
    #pragma unroll
    for (int in = 0; in < 4; in++) {
        int cg = nBase + (warp >> 1) * 32 + in * 8 + 2 * (lane & 3);
        bv2[in][0] = bias[cg]; bv2[in][1] = bias[cg + 1];
    }

    if (blockIdx.z <= 1) {
        // transposed per-head store: [bh][dh][l]
        #pragma unroll
        for (int im = 0; im < 4; im++) {
            int rg0 = mBase + (warp & 1) * 64 + im * 16 + (lane >> 2);
            int rg1 = rg0 + 8;
            int b0 = rg0 / 71, l0 = rg0 - b0 * 71;
            int b1 = rg1 / 71, l1 = rg1 - b1 * 71;
            #pragma unroll
            for (int in = 0; in < 4; in++) {
                int cg = nBase + (warp >> 1) * 32 + in * 8 + 2 * (lane & 3);
                int h = cg >> 6, dh = cg & 63;
                size_t base0 = ((size_t)((b0 * 8 + h) * 64 + dh)) * 71 + l0;
                size_t base1 = ((size_t)((b1 * 8 + h) * 64 + dh)) * 71 + l1;
                out[base0]      = (c[im][in][0] + bv2[in][0]) * scale;
                out[base0 + 71] = (c[im][in][1] + bv2[in][1]) * scale;
                out[base1]      = (c[im][in][2] + bv2[in][0]) * scale;
                out[base1 + 71] = (c[im][in][3] + bv2[in][1]) * scale;
            }
        }
    } else {
        #pragma unroll
        for (int im = 0; im < 4; im++) {
            int rg0 = mBase + (warp & 1) * 64 + im * 16 + (lane >> 2);
            int rg1 = rg0 + 8;
            int b0 = rg0 / 71, l0 = rg0 - b0 * 71;
            int b1 = rg1 / 71, l1 = rg1 - b1 * 71;
            #pragma unroll
            for (int in = 0; in < 4; in++) {
                int cg = nBase + (warp >> 1) * 32 + in * 8 + 2 * (lane & 3);
                int h = cg >> 6, dh = cg & 63;
                float2 v0 = make_float2(c[im][in][0] + bv2[in][0], c[im][in][1] + bv2[in][1]);
                float2 v1 = make_float2(c[im][in][2] + bv2[in][0], c[im][in][3] + bv2[in][1]);
                *(float2*)&out[(((size_t)(b0 * 8 + h) * 71 + l0) << 6) + dh] = v0;
                *(float2*)&out[(((size_t)(b1 * 8 + h) * 71 + l1) << 6) + dh] = v1;
            }
        }
    }
}

// ---------------------------------------------------------------------------
// Output projection: grid (4, 284).
// ---------------------------------------------------------------------------
__global__ void __launch_bounds__(256) out_gemm_kernel(
    float* __restrict__ out, const float* __restrict__ Wo,
    const float* __restrict__ bo)
{
    float c[4][4][4];
    gemm_tf32_ctile(g_attnT, Wo, c);

    const int lane = threadIdx.x & 31, warp = threadIdx.x >> 5;
    const int mBase = blockIdx.y * 128, nBase = blockIdx.x * 128;

    float bv2[4][2];
    #pragma unroll
    for (int in = 0; in < 4; in++) {
        int cg = nBase + (warp >> 1) * 32 + in * 8 + 2 * (lane & 3);
        bv2[in][0] = bo[cg]; bv2[in][1] = bo[cg + 1];
    }
    #pragma unroll
    for (int im = 0; im < 4; im++) {
        int rg0 = mBase + (warp & 1) * 64 + im * 16 + (lane >> 2);
        int rg1 = rg0 + 8;
        #pragma unroll
        for (int in = 0; in < 4; in++) {
            int cg = nBase + (warp >> 1) * 32 + in * 8 + 2 * (lane & 3);
            float2 v0 = make_float2(c[im][in][0] + bv2[in][0], c[im][in][1] + bv2[in][1]);
            float2 v1 = make_float2(c[im][in][2] + bv2[in][0], c[im][in][3] + bv2[in][1]);
            *(float2*)&out[(size_t)rg0 * 512 + cg] = v0;
            *(float2*)&out[(size_t)rg1 * 512 + cg] = v1;
        }
    }
}

// ---------------------------------------------------------------------------
// Tensorized attention core. CTA = 2 heads (512 thr). Grid = 2048.
// Per-head region (17600 floats): sS [72][88] at +0; union U at +6336:
//   stage0-1: sQt [64][88] + sKt [64][88]; stage2-3: sH [128][88];
//   stage5: sV [72][72].
// Shared (at 35200): w1s [72][136], w2s [128][72], b1s[128], b2s[72].
// Total 54408 floats = 217632 B.
// ---------------------------------------------------------------------------
__global__ void __launch_bounds__(512, 1) attn_kernel(
    const float* __restrict__ w1, const float* __restrict__ b1,
    const float* __restrict__ w2, const float* __restrict__ b2)
{
    extern __shared__ float sm[];
    const int tid  = threadIdx.x;
    const int lane = tid & 31;
    const int warp = tid >> 5;      // 0..15
    const int half = warp >> 3;     // 0/1
    const int w    = warp & 7;      // 0..7
    const int htid = tid & 255;
    const int bh   = blockIdx.x * 2 + half;
    const int bidx = bh >> 3, hidx = bh & 7;

    float* sS  = sm + half * 17600;
    float* U   = sS + 6336;
    float* w1s = sm + 35200;
    float* w2s = w1s + 9792;
    float* b1s = w2s + 9216;
    float* b2s = b1s + 128;

    // ---- shared weight loads (all 512 threads) ----
    for (int i = tid; i < 72 * 128; i += 512) {
        int k = i >> 7, n = i & 127;
        w1s[k * 136 + n] = (k < 71) ? to_tf32(w1[k * 128 + n]) : 0.f;
    }
    for (int i = tid; i < 128 * 72; i += 512) {
        int k = i / 72, n = i - k * 72;
        w2s[k * 72 + n] = (n < 71) ? to_tf32(w2[k * 71 + n]) : 0.f;
    }
    if (tid < 128) b1s[tid] = b1[tid];
    if (tid < 72)  b2s[tid] = (tid < 71) ? b2[tid] : 0.f;

    // ---- load Q^T, K^T (coalesced LDG, conflict-free STS) ----
    {
        float* sQt = U;
        float* sKt = U + 5632;
        const float* Qg = g_Qt + (size_t)bh * HEAD_ELEMS;
        const float* Kg = g_Kt + (size_t)bh * HEAD_ELEMS;
        for (int i = htid; i < HEAD_ELEMS; i += 256) {
            int dh = i / 71, l = i - dh * 71;
            sQt[dh * 88 + l] = to_tf32(Qg[i]);
            sKt[dh * 88 + l] = to_tf32(Kg[i]);
        }
        for (int i = htid; i < 64 * 17; i += 256) {   // zero pad cols 71..87
            int dh = i / 17, l = 71 + (i - dh * 17);
            sQt[dh * 88 + l] = 0.f;
            sKt[dh * 88 + l] = 0.f;
        }
    }
    __syncthreads();

    // ---- stage 1: S = Q @ K^T  (M=80, N=72, K=64) -> sS[key][query] tf32 ----
    {
        const float* sQt = U;
        const float* sKt = U + 5632;
        const int nslots = (w == 0) ? 2 : 1;
        float acc[2][5][4] = {};
        for (int ks = 0; ks < 8; ks++) {
            int kk = ks * 8 + (lane & 3);
            unsigned bfr[2][2];
            for (int s = 0; s < nslots; s++) { LDB(bfr[s], sKt, 88, w + s * 8, kk); }
            #pragma unroll
            for (int mt = 0; mt < 5; mt++) {
                unsigned afr[4];
                LDA(afr, sQt, 88, mt, kk);
                for (int s = 0; s < nslots; s++) mma_tf32(acc[s][mt], afr, bfr[s]);
            }
        }
        for (int s = 0; s < nslots; s++) {
            int n0 = (w + s * 8) * 8 + 2 * (lane & 3);
            #pragma unroll
            for (int mt = 0; mt < 5; mt++) {
                int r = mt * 16 + (lane >> 2);
                sS[n0 * 88 + r]           = to_tf32(acc[s][mt][0]);
                sS[(n0 + 1) * 88 + r]     = to_tf32(acc[s][mt][1]);
                sS[n0 * 88 + r + 8]       = to_tf32(acc[s][mt][2]);
                sS[(n0 + 1) * 88 + r + 8] = to_tf32(acc[s][mt][3]);
            }
        }
    }
    __syncthreads();

    // ---- stage 2: H = gelu(S @ w1 + b1)  (M=80, N=128, K=72) -> sH[ff][q] ----
    {
        float* sH = U;
        float acc[2][5][4] = {};
        for (int ks = 0; ks < 9; ks++) {
            int kk = ks * 8 + (lane & 3);
            unsigned bfr[2][2];
            LDB(bfr[0], w1s, 136, w, kk);
            LDB(bfr[1], w1s, 136, w + 8, kk);
            #pragma unroll
            for (int mt = 0; mt < 5; mt++) {
                unsigned afr[4];
                LDA(afr, sS, 88, mt, kk);
                mma_tf32(acc[0][mt], afr, bfr[0]);
                mma_tf32(acc[1][mt], afr, bfr[1]);
            }
        }
        #pragma unroll
        for (int s = 0; s < 2; s++) {
            int n0 = (w + s * 8) * 8 + 2 * (lane & 3);
            float bb0 = b1s[n0], bb1 = b1s[n0 + 1];
            #pragma unroll
            for (int mt = 0; mt < 5; mt++) {
                int r = mt * 16 + (lane >> 2);
                float x0 = acc[s][mt][0] + bb0;
                float x1 = acc[s][mt][1] + bb1;
                float x2 = acc[s][mt][2] + bb0;
                float x3 = acc[s][mt][3] + bb1;
                sH[n0 * 88 + r] =
                    to_tf32(0.5f * x0 * (1.f + erff(x0 * 0.70710678118654752f)));
                sH[(n0 + 1) * 88 + r] =
                    to_tf32(0.5f * x1 * (1.f + erff(x1 * 0.70710678118654752f)));
                sH[n0 * 88 + r + 8] =
                    to_tf32(0.5f * x2 * (1.f + erff(x2 * 0.70710678118654752f)));
                sH[(n0 + 1) * 88 + r + 8] =
                    to_tf32(0.5f * x3 * (1.f + erff(x3 * 0.70710678118654752f)));
            }
        }
    }
    __syncthreads();

    // ---- stage 3: S += H @ w2 + b2  (M=80, N=72, K=128) ----
    {
        const float* sH = U;
        const int nslots = (w == 0) ? 2 : 1;
        float acc[2][5][4] = {};
        for (int ks = 0; ks < 16; ks++) {
            int kk = ks * 8 + (lane & 3);
            unsigned bfr[2][2];
            for (int s = 0; s < nslots; s++) { LDB(bfr[s], w2s, 72, w + s * 8, kk); }
            #pragma unroll
            for (int mt = 0; mt < 5; mt++) {
                unsigned afr[4];
                LDA(afr, sH, 88, mt, kk);
                for (int s = 0; s < nslots; s++) mma_tf32(acc[s][mt], afr, bfr[s]);
            }
        }
        for (int s = 0; s < nslots; s++) {
            int n0 = (w + s * 8) * 8 + 2 * (lane & 3);
            float bb0 = b2s[n0], bb1 = b2s[n0 + 1];
            #pragma unroll
            for (int mt = 0; mt < 5; mt++) {
                int r = mt * 16 + (lane >> 2);
                sS[n0 * 88 + r]           += acc[s][mt][0] + bb0;
                sS[(n0 + 1) * 88 + r]     += acc[s][mt][1] + bb1;
                sS[n0 * 88 + r + 8]       += acc[s][mt][2] + bb0;
                sS[(n0 + 1) * 88 + r + 8] += acc[s][mt][3] + bb1;
            }
        }
    }
    __syncthreads();

    // ---- V load into U (overwrites dead sH) + softmax on sS columns ----
    {
        float* sV = U;
        const float* Vg = g_V + (size_t)bh * HEAD_ELEMS;
        for (int i = htid; i < HEAD_ELEMS; i += 256) {
            int l = i >> 6, dh = i & 63;
            sV[l * 72 + dh] = to_tf32(Vg[i]);
        }
    }
    if (htid < 71) {
        const int q = htid;
        float mx = -1e30f;
        for (int k = 0; k < 71; k++) mx = fmaxf(mx, sS[k * 88 + q]);
        float ssum = 0.f;
        for (int k = 0; k < 71; k++) {
            float e = __expf(sS[k * 88 + q] - mx);
            sS[k * 88 + q] = e;
            ssum += e;
        }
        float inv = 1.f / ssum;
        for (int k = 0; k < 71; k++) sS[k * 88 + q] = to_tf32(sS[k * 88 + q] * inv);
    }
    __syncthreads();

    // ---- stage 5: attn = P @ V  (M=80, N=64, K=72) -> g_attnT[d][m] ----
    {
        const float* sV = U;
        float acc[5][4] = {};
        for (int ks = 0; ks < 9; ks++) {
            int kk = ks * 8 + (lane & 3);
            unsigned bfr[2];
            LDB(bfr, sV, 72, w, kk);
            #pragma unroll
            for (int mt = 0; mt < 5; mt++) {
                unsigned afr[4];
                LDA(afr, sS, 88, mt, kk);
                mma_tf32(acc[mt], afr, bfr);
            }
        }
        const int n0 = w * 8 + 2 * (lane & 3);
        const size_t d0 = (size_t)(hidx * 64 + n0);
        #pragma unroll
        for (int mt = 0; mt < 5; mt++) {
            int r = mt * 16 + (lane >> 2);
            if (r < 71) {
                size_t mg = (size_t)bidx * 71 + r;
                g_attnT[d0 * MROWS + mg]       = to_tf32(acc[mt][0]);
                g_attnT[(d0 + 1) * MROWS + mg] = to_tf32(acc[mt][1]);
            }
            if (r + 8 < 71) {
                size_t mg = (size_t)bidx * 71 + r + 8;
                g_attnT[d0 * MROWS + mg]       = to_tf32(acc[mt][2]);
                g_attnT[(d0 + 1) * MROWS + mg] = to_tf32(acc[mt][3]);
            }
        }
    }
}

// ---------------------------------------------------------------------------
extern "C" void kernel_launch(void* const* d_in, const int* in_sizes, int n_in,
                              void* d_out, int out_size)
{
    const float* query = (const float*)d_in[0];
    const float* key   = (const float*)d_in[1];
    const float* value = (const float*)d_in[2];
    const float* Wq = (const float*)d_in[3];
    const float* bq = (const float*)d_in[4];
    const float* Wk = (const float*)d_in[5];
    const float* bk = (const float*)d_in[6];
    const float* Wv = (const float*)d_in[7];
    const float* bv = (const float*)d_in[8];
    const float* Wo = (const float*)d_in[9];
    const float* bo = (const float*)d_in[10];
    const float* sf_w1 = (const float*)d_in[11];
    const float* sf_b1 = (const float*)d_in[12];
    const float* sf_w2 = (const float*)d_in[13];
    const float* sf_b2 = (const float*)d_in[14];
    float* out = (float*)d_out;

    float *dTq, *dTk, *dTv;
    cudaGetSymbolAddress((void**)&dTq, g_Tq);
    cudaGetSymbolAddress((void**)&dTk, g_Tk);
    cudaGetSymbolAddress((void**)&dTv, g_Tv);

    const int gemm_smem = 17408 * sizeof(float);    // 69632 B
    cudaFuncSetAttribute(qkv_gemm_kernel, cudaFuncAttributeMaxDynamicSharedMemorySize, gemm_smem);
    cudaFuncSetAttribute(out_gemm_kernel, cudaFuncAttributeMaxDynamicSharedMemorySize, gemm_smem);
    const int attn_smem = 54408 * sizeof(float);    // 217632 B
    cudaFuncSetAttribute(attn_kernel, cudaFuncAttributeMaxDynamicSharedMemorySize, attn_smem);

    // 1) transpose+cvt activations
    dim3 gt(MROWS / 32, 16, 3);
    transpose_cvt_kernel<<<gt, 256>>>(query, key, value, dTq, dTk, dTv);

    // 2) QKV projections (tf32 tensor cores)
    dim3 g1(4, 284, 3);
    qkv_gemm_kernel<<<g1, 256, gemm_smem>>>(Wq, bq, Wk, bk, Wv, bv);

    // 3) tensorized attention core (2 heads per CTA)
    attn_kernel<<<NHEADS / 2, 512, attn_smem>>>(sf_w1, sf_b1, sf_w2, sf_b2);

    // 4) output projection
    dim3 g3(4, 284);
    out_gemm_kernel<<<g3, 256, gemm_smem>>>(out, Wo, bo);
}